// round 14
// baseline (speedup 1.0000x reference)
#include <cuda_runtime.h>
#include <cuda_fp16.h>
#include <cstdint>

// ---------------- problem constants ----------------
#define Bc   2
#define Tc   4096
#define Ec   512
#define Hc   8
#define Dc   64
#define FFc  2048
#define Lc   2
#define WINc 16
#define NW   33
#define ROWS (Bc*Tc)      // 8192
#define EPSc 1e-5f
#define QKVN (3*Ec)       // 1536

#define WT_QKV_OFF 0
#define WT_WO_OFF  (3*Ec*Ec)
#define WT_W1_OFF  (4*Ec*Ec)
#define WT_W2_OFF  (WT_W1_OFF + FFc*Ec)
#define WT_LAYER   (WT_W2_OFF + Ec*FFc)

// ---------------- scratch ----------------
__device__ __half g_h   [(size_t)ROWS*Ec];
__device__ __half g_qkv [(size_t)ROWS*QKVN];
__device__ __half g_ao  [(size_t)ROWS*Ec];
__device__ __half g_ff  [(size_t)ROWS*FFc];
__device__ __half g_wt  [(size_t)Lc*WT_LAYER];

// ---------------- helpers ----------------
__device__ __forceinline__ uint32_t smem_u32(const void* p) {
    uint32_t a;
    asm("{ .reg .u64 t; cvta.to.shared.u64 t, %1; cvt.u32.u64 %0, t; }" : "=r"(a) : "l"(p));
    return a;
}
#define SW128(x) ((x) ^ (((x) >> 3) & 0x70))

#define CP16(dst, src) \
    asm volatile("cp.async.cg.shared.global [%0], [%1], 16;" :: "r"(dst), "l"(src) : "memory")
#define CPCOMMIT() asm volatile("cp.async.commit_group;" ::: "memory")

__device__ __forceinline__ void ldmx4(uint32_t& r0, uint32_t& r1, uint32_t& r2, uint32_t& r3,
                                      uint32_t addr) {
    asm volatile("ldmatrix.sync.aligned.m8n8.x4.shared.b16 {%0,%1,%2,%3}, [%4];"
                 : "=r"(r0), "=r"(r1), "=r"(r2), "=r"(r3) : "r"(addr));
}
__device__ __forceinline__ void mma16816(float* c, const uint32_t* a, const uint32_t* b) {
    asm volatile("mma.sync.aligned.m16n8k16.row.col.f32.f16.f16.f32 "
                 "{%0,%1,%2,%3}, {%4,%5,%6,%7}, {%8,%9}, {%0,%1,%2,%3};"
                 : "+f"(c[0]), "+f"(c[1]), "+f"(c[2]), "+f"(c[3])
                 : "r"(a[0]), "r"(a[1]), "r"(a[2]), "r"(a[3]), "r"(b[0]), "r"(b[1]));
}

// ---------------- fused embedding + LN1(layer 0) ----------------------------
__global__ void embed_ln_kernel(const int* __restrict__ tokens,
                                const float* __restrict__ tok_emb,
                                const float* __restrict__ pos_emb,
                                const float* __restrict__ g,
                                const float* __restrict__ b,
                                float* __restrict__ x,
                                __half* __restrict__ h) {
    int warp = (blockIdx.x * blockDim.x + threadIdx.x) >> 5;
    int lane = threadIdx.x & 31;
    if (warp >= ROWS) return;
    int t   = warp & (Tc - 1);
    int tok = tokens[warp];
    const float* te = tok_emb + (size_t)tok * Ec;
    const float* pe = pos_emb + (size_t)t * Ec;
    float v[16];
    float s = 0.f;
#pragma unroll
    for (int i = 0; i < 16; i++) {
        int idx = lane + i * 32;
        v[i] = te[idx] + pe[idx];
        s += v[i];
    }
    size_t rb = (size_t)warp * Ec;
#pragma unroll
    for (int i = 0; i < 16; i++) x[rb + lane + i * 32] = v[i];
#pragma unroll
    for (int o = 16; o > 0; o >>= 1) s += __shfl_xor_sync(0xffffffffu, s, o);
    float mean = s * (1.f / Ec);
    float ss = 0.f;
#pragma unroll
    for (int i = 0; i < 16; i++) { float d = v[i] - mean; ss += d * d; }
#pragma unroll
    for (int o = 16; o > 0; o >>= 1) ss += __shfl_xor_sync(0xffffffffu, ss, o);
    float inv = rsqrtf(ss * (1.f / Ec) + EPSc);
#pragma unroll
    for (int i = 0; i < 16; i++) {
        int idx = lane + i * 32;
        h[rb + idx] = __float2half_rn((v[i] - mean) * inv * g[idx] + b[idx]);
    }
}

// ---------------- layernorm -> fp16 ----------------
__global__ void ln_kernel(const float* __restrict__ x,
                          const float* __restrict__ g,
                          const float* __restrict__ b,
                          __half* __restrict__ y) {
    int warp = (blockIdx.x * blockDim.x + threadIdx.x) >> 5;
    int lane = threadIdx.x & 31;
    if (warp >= ROWS) return;
    const float* xr = x + (size_t)warp * Ec;
    float v[16];
    float s = 0.f;
#pragma unroll
    for (int i = 0; i < 16; i++) { v[i] = xr[lane + i * 32]; s += v[i]; }
#pragma unroll
    for (int o = 16; o > 0; o >>= 1) s += __shfl_xor_sync(0xffffffffu, s, o);
    float mean = s * (1.f / Ec);
    float ss = 0.f;
#pragma unroll
    for (int i = 0; i < 16; i++) { float d = v[i] - mean; ss += d * d; }
#pragma unroll
    for (int o = 16; o > 0; o >>= 1) ss += __shfl_xor_sync(0xffffffffu, ss, o);
    float inv = rsqrtf(ss * (1.f / Ec) + EPSc);
    size_t rb = (size_t)warp * Ec;
#pragma unroll
    for (int i = 0; i < 16; i++) {
        int idx = lane + i * 32;
        y[rb + idx] = __float2half_rn((v[i] - mean) * inv * g[idx] + b[idx]);
    }
}

// ---------------- fused weight prep (fp16 transpose) ----------------
__global__ void prep_kernel(const float* __restrict__ Wq, const float* __restrict__ Wk,
                            const float* __restrict__ Wv, const float* __restrict__ Wo,
                            const float* __restrict__ W1, const float* __restrict__ W2,
                            __half* __restrict__ thi) {
    int l = blockIdx.z, y = blockIdx.y;
    int K = (y == 5) ? FFc : Ec;
    int N = (y == 4) ? FFc : Ec;
    int ntiles = N >> 5;
    int nt = blockIdx.x % ntiles;
    int kt = blockIdx.x / ntiles;
    if (kt >= (K >> 5)) return;

    const float* W; size_t doff;
    switch (y) {
        case 0: W = Wq + (size_t)l * Ec * Ec;  doff = WT_QKV_OFF;            break;
        case 1: W = Wk + (size_t)l * Ec * Ec;  doff = WT_QKV_OFF + Ec * Ec;  break;
        case 2: W = Wv + (size_t)l * Ec * Ec;  doff = WT_QKV_OFF + 2*Ec*Ec;  break;
        case 3: W = Wo + (size_t)l * Ec * Ec;  doff = WT_WO_OFF;             break;
        case 4: W = W1 + (size_t)l * Ec * FFc; doff = WT_W1_OFF;             break;
        default:W = W2 + (size_t)l * FFc * Ec; doff = WT_W2_OFF;             break;
    }
    doff += (size_t)l * WT_LAYER;

    __shared__ float tile[32][33];
    int n0 = nt * 32, k0 = kt * 32;
    int tx = threadIdx.x, ty = threadIdx.y;
#pragma unroll
    for (int i = 0; i < 32; i += 8)
        tile[ty + i][tx] = W[(size_t)(k0 + ty + i) * N + n0 + tx];
    __syncthreads();
#pragma unroll
    for (int i = 0; i < 32; i += 8) {
        float v = tile[tx][ty + i];
        thi[doff + (size_t)(n0 + ty + i) * K + k0 + tx] = __float2half_rn(v);
    }
}

// ---------------- mma.sync GEMM: CTA 128x128, warp 64x32, 2 CTAs/SM ----------
#define GBM 128
#define GBN 128
#define GBK 64
#define A_OFF   0
#define B_OFF   16384
#define GSTG    32768
#define NSTAGE  3
#define GEMM_SMEM (NSTAGE*GSTG)

__device__ __forceinline__ void load_chunk(
    uint32_t base, int tid, int rowA0, int rowB0, int k0, int K,
    const __half* __restrict__ A, const __half* __restrict__ B) {
#pragma unroll
    for (int i = tid; i < 1024; i += 256) {
        int r = i >> 3, j = i & 7;
        uint32_t sw = SW128((uint32_t)((r << 7) + (j << 4)));
        CP16(base + A_OFF + sw, A + (size_t)(rowA0 + r) * K + k0 + j * 8);
    }
#pragma unroll
    for (int i = tid; i < 1024; i += 256) {
        int r = i >> 3, j = i & 7;
        uint32_t sw = SW128((uint32_t)((r << 7) + (j << 4)));
        CP16(base + B_OFF + sw, B + (size_t)(rowB0 + r) * K + k0 + j * 8);
    }
}

template <int EPI>
__global__ __launch_bounds__(256, 2)
void mma_gemm(const __half* __restrict__ A, const __half* __restrict__ B,
              const float* __restrict__ bias, const float* __restrict__ res,
              float* __restrict__ outF, __half* __restrict__ outH,
              int N, int K) {
    extern __shared__ char smem[];
    uint32_t sb = smem_u32(smem);
    int tid = threadIdx.x, wid = tid >> 5, lane = tid & 31;

    int rowA0 = blockIdx.y * GBM;
    int rowB0 = blockIdx.x * GBN;
    int warpM0 = (wid >> 2) * 64;
    int warpN0 = (wid & 3) * 32;
    const int KC = K / GBK;

    float acc[4][4][4];
#pragma unroll
    for (int i = 0; i < 4; i++)
#pragma unroll
        for (int j = 0; j < 4; j++)
#pragma unroll
            for (int r = 0; r < 4; r++) acc[i][j][r] = 0.f;

    load_chunk(sb,        tid, rowA0, rowB0, 0,   K, A, B); CPCOMMIT();
    load_chunk(sb + GSTG, tid, rowA0, rowB0, GBK, K, A, B); CPCOMMIT();

    int mat  = lane >> 3;
    int mrow = lane & 7;
    int rsel = (mat & 1) * 8 + mrow;
    int csel = mat >> 1;

    for (int c = 0; c < KC; c++) {
        uint32_t base = sb + (uint32_t)(c % NSTAGE) * GSTG;
        if (c < KC - 1) asm volatile("cp.async.wait_group 1;" ::: "memory");
        else            asm volatile("cp.async.wait_group 0;" ::: "memory");
        __syncthreads();
        if (c + 2 < KC) {
            load_chunk(sb + (uint32_t)((c + 2) % NSTAGE) * GSTG,
                       tid, rowA0, rowB0, (c + 2) * GBK, K, A, B);
            CPCOMMIT();
        }

#pragma unroll
        for (int kk = 0; kk < 4; kk++) {
            int chunk = 2 * kk + csel;
            uint32_t ah[4][4];
#pragma unroll
            for (int mi = 0; mi < 4; mi++) {
                uint32_t sw = SW128((uint32_t)((warpM0 + mi * 16 + rsel) << 7) + (chunk << 4));
                ldmx4(ah[mi][0], ah[mi][1], ah[mi][2], ah[mi][3], base + A_OFF + sw);
            }
            uint32_t bf[4][2];
#pragma unroll
            for (int bj = 0; bj < 2; bj++) {
                uint32_t sw = SW128((uint32_t)((warpN0 + bj * 16 + rsel) << 7) + (chunk << 4));
                uint32_t r0, r1, r2, r3;
                ldmx4(r0, r1, r2, r3, base + B_OFF + sw);
                bf[2*bj][0] = r0; bf[2*bj][1] = r2; bf[2*bj+1][0] = r1; bf[2*bj+1][1] = r3;
            }
#pragma unroll
            for (int mi = 0; mi < 4; mi++)
#pragma unroll
                for (int nf = 0; nf < 4; nf++)
                    mma16816(acc[mi][nf], ah[mi], bf[nf]);
        }
    }

    int grp = lane >> 2;
    int qd  = lane & 3;
#pragma unroll
    for (int mi = 0; mi < 4; mi++) {
#pragma unroll
        for (int half = 0; half < 2; half++) {
            int m = rowA0 + warpM0 + mi * 16 + half * 8 + grp;
            size_t orow = (size_t)m * N;
#pragma unroll
            for (int nf = 0; nf < 4; nf++) {
                int n = rowB0 + warpN0 + nf * 8 + qd * 2;
                float v0 = acc[mi][nf][half * 2 + 0];
                float v1 = acc[mi][nf][half * 2 + 1];
                if (EPI == 0) {
                    __half2 hh;
                    hh.x = __float2half_rn(v0);
                    hh.y = __float2half_rn(v1);
                    *(__half2*)(outH + orow + n) = hh;
                } else if (EPI == 2) {
                    float2 rr = *(const float2*)(res + orow + n);
                    float2 vv;
                    vv.x = v0 + bias[n]     + rr.x;
                    vv.y = v1 + bias[n + 1] + rr.y;
                    *(float2*)(outF + orow + n) = vv;
                } else {
                    v0 = fmaxf(v0 + bias[n],     0.f);
                    v1 = fmaxf(v1 + bias[n + 1], 0.f);
                    __half2 hh;
                    hh.x = __float2half_rn(v0);
                    hh.y = __float2half_rn(v1);
                    *(__half2*)(outH + orow + n) = hh;
                }
            }
        }
    }
}

// ---------------- sliding-window attention: fp32-staged K, fp32 q ------------
#define ATT 64
#define AROWS (ATT + 2*WINc)   // 96
#define KPITCHF 68             // floats; 17 float4-units (odd) -> conflict-free
#define VPITCH  66             // halves; 33 words (odd) -> conflict-free

__global__ void attn_kernel(const __half* __restrict__ qkv,
                            const int* __restrict__ mask,
                            __half* __restrict__ ao) {
    __shared__ float  sKf[AROWS * KPITCHF];   // 26112 B
    __shared__ __half sV [AROWS * VPITCH];    // 12672 B
    __shared__ float  sq [8][64];             // per-warp fp32 q
    __shared__ float  sp [8][40];
    __shared__ int    sM [AROWS];

    int bid  = blockIdx.x;
    int tile = bid & (Tc / ATT - 1);
    int h    = (bid >> 6) & (Hc - 1);
    int b    = bid >> 9;
    int t0   = tile * ATT;
    int tid  = threadIdx.x;

    if (tid < AROWS) {
        int tc = t0 - WINc + tid;
        sM[tid] = (tc >= 0 && tc < Tc) ? mask[b * Tc + tc] : 0;
    }
    for (int i = tid; i < AROWS * 32; i += 256) {
        int r = i >> 5, j = i & 31;
        int tc = t0 - WINc + r;
        float2 kf = make_float2(0.f, 0.f);
        uint32_t vv = 0;
        if (tc >= 0 && tc < Tc) {
            const __half* kr = qkv + (size_t)(b * Tc + tc) * QKVN + Ec + h * Dc;
            const __half* vr = qkv + (size_t)(b * Tc + tc) * QKVN + 2 * Ec + h * Dc;
            kf = __half22float2(*(const __half2*)(kr + j * 2));
            vv = *(const uint32_t*)(vr + j * 2);
        }
        sKf[r * KPITCHF + j * 2 + 0] = kf.x;
        sKf[r * KPITCHF + j * 2 + 1] = kf.y;
        *(uint32_t*)(sV + r * VPITCH + j * 2) = vv;
    }
    __syncthreads();

    int wid = tid >> 5, lane = tid & 31;
    for (int tt = wid; tt < ATT; tt += 8) {
        int t = t0 + tt;
        const __half2* q2 = (const __half2*)(qkv + (size_t)(b * Tc + t) * QKVN + h * Dc);

        // stage q as fp32 (one conversion per token per lane)
        float2 qv = __half22float2(q2[lane]);
        sq[wid][2 * lane]     = qv.x;
        sq[wid][2 * lane + 1] = qv.y;
        __syncwarp();

        // phase A: lane w computes score for window w via float4 smem reads
        int w = lane;
        bool valid = sM[tt + w] > 0;
        float s = -1e9f;
        {
            const float4* qf4 = (const float4*)&sq[wid][0];
            const float4* kf4 = (const float4*)(sKf + (tt + w) * KPITCHF);
            float p = 0.f;
#pragma unroll
            for (int j = 0; j < 16; j++) {
                float4 q4 = qf4[j];
                float4 k4 = kf4[j];
                p += q4.x * k4.x + q4.y * k4.y + q4.z * k4.z + q4.w * k4.w;
            }
            if (valid) s = p * 0.125f;
        }
        // window 32 cooperatively
        float s32 = -1e9f;
        {
            bool v2 = sM[tt + 32] > 0;
            const float* kr = sKf + (tt + 32) * KPITCHF + 2 * lane;
            float pp = qv.x * kr[0] + qv.y * kr[1];
#pragma unroll
            for (int o = 16; o > 0; o >>= 1) pp += __shfl_xor_sync(0xffffffffu, pp, o);
            if (v2) s32 = pp * 0.125f;
        }
        float m = s;
#pragma unroll
        for (int o = 16; o > 0; o >>= 1) m = fmaxf(m, __shfl_xor_sync(0xffffffffu, m, o));
        m = fmaxf(m, s32);
        float e  = __expf(s - m);
        float es = e;
#pragma unroll
        for (int o = 16; o > 0; o >>= 1) es += __shfl_xor_sync(0xffffffffu, es, o);
        float e32 = __expf(s32 - m);
        float inv = 1.f / (es + e32);
        sp[wid][lane] = e;
        if (lane == 0) sp[wid][32] = e32;
        __syncwarp();

        // phase B: lane covers dims 2*lane, 2*lane+1
        float ox = 0.f, oy = 0.f;
#pragma unroll
        for (int ww = 0; ww < NW; ww++) {
            float a = sp[wid][ww];
            float2 vf = __half22float2(*(const __half2*)(sV + (tt + ww) * VPITCH + 2 * lane));
            ox += a * vf.x;
            oy += a * vf.y;
        }
        size_t ob = (size_t)(b * Tc + t) * Ec + h * Dc;
        __half2 oh;
        oh.x = __float2half_rn(ox * inv);
        oh.y = __float2half_rn(oy * inv);
        *(__half2*)(ao + ob + 2 * lane) = oh;
        __syncwarp();
    }
}

// ---------------- orchestration ----------------
extern "C" void kernel_launch(void* const* d_in, const int* in_sizes, int n_in,
                              void* d_out, int out_size) {
    const int*   tokens  = (const int*)  d_in[0];
    const int*   attmask = (const int*)  d_in[1];
    const float* tok_emb = (const float*)d_in[2];
    const float* pos_emb = (const float*)d_in[3];
    const float* Wq      = (const float*)d_in[4];
    const float* Wk      = (const float*)d_in[5];
    const float* Wv      = (const float*)d_in[6];
    const float* Wo      = (const float*)d_in[7];
    const float* bo      = (const float*)d_in[8];
    const float* ln1_g   = (const float*)d_in[9];
    const float* ln1_b   = (const float*)d_in[10];
    const float* ln2_g   = (const float*)d_in[11];
    const float* ln2_b   = (const float*)d_in[12];
    const float* W1      = (const float*)d_in[13];
    const float* b1      = (const float*)d_in[14];
    const float* W2      = (const float*)d_in[15];
    const float* b2      = (const float*)d_in[16];

    float* x = (float*)d_out;

    __half *h, *qkv, *ao, *ff, *wt;
    cudaGetSymbolAddress((void**)&h,   g_h);
    cudaGetSymbolAddress((void**)&qkv, g_qkv);
    cudaGetSymbolAddress((void**)&ao,  g_ao);
    cudaGetSymbolAddress((void**)&ff,  g_ff);
    cudaGetSymbolAddress((void**)&wt,  g_wt);

    cudaFuncSetAttribute(mma_gemm<0>, cudaFuncAttributeMaxDynamicSharedMemorySize, GEMM_SMEM);
    cudaFuncSetAttribute(mma_gemm<1>, cudaFuncAttributeMaxDynamicSharedMemorySize, GEMM_SMEM);
    cudaFuncSetAttribute(mma_gemm<2>, cudaFuncAttributeMaxDynamicSharedMemorySize, GEMM_SMEM);

    prep_kernel<<<dim3(1024, 6, Lc), dim3(32, 8)>>>(Wq, Wk, Wv, Wo, W1, W2, wt);
    embed_ln_kernel<<<1024, 256>>>(tokens, tok_emb, pos_emb, ln1_g, ln1_b, x, h);

    for (int l = 0; l < Lc; l++) {
        const __half* w = wt + (size_t)l * WT_LAYER;

        if (l > 0)
            ln_kernel<<<1024, 256>>>(x, ln1_g + l * Ec, ln1_b + l * Ec, h);

        mma_gemm<0><<<dim3(QKVN / GBN, ROWS / GBM), 256, GEMM_SMEM>>>(
            h, w + WT_QKV_OFF, nullptr, nullptr, nullptr, qkv, QKVN, Ec);

        attn_kernel<<<Bc * Hc * (Tc / ATT), 256>>>(qkv, attmask, ao);

        mma_gemm<2><<<dim3(Ec / GBN, ROWS / GBM), 256, GEMM_SMEM>>>(
            ao, w + WT_WO_OFF, bo + l * Ec, x, x, nullptr, Ec, Ec);

        ln_kernel<<<1024, 256>>>(x, ln2_g + l * Ec, ln2_b + l * Ec, h);

        mma_gemm<1><<<dim3(FFc / GBN, ROWS / GBM), 256, GEMM_SMEM>>>(
            h, w + WT_W1_OFF, b1 + l * FFc, nullptr, nullptr, ff, FFc, Ec);

        mma_gemm<2><<<dim3(Ec / GBN, ROWS / GBM), 256, GEMM_SMEM>>>(
            ff, w + WT_W2_OFF, b2 + l * Ec, x, x, nullptr, Ec, FFc);
    }
    (void)in_sizes; (void)n_in; (void)out_size;
}

// round 15
// speedup vs baseline: 1.0639x; 1.0639x over previous
#include <cuda_runtime.h>
#include <cuda_fp16.h>
#include <cstdint>

// ---------------- problem constants ----------------
#define Bc   2
#define Tc   4096
#define Ec   512
#define Hc   8
#define Dc   64
#define FFc  2048
#define Lc   2
#define WINc 16
#define NW   33
#define ROWS (Bc*Tc)      // 8192
#define EPSc 1e-5f
#define QKVN (3*Ec)       // 1536

#define WT_QKV_OFF 0
#define WT_WO_OFF  (3*Ec*Ec)
#define WT_W1_OFF  (4*Ec*Ec)
#define WT_W2_OFF  (WT_W1_OFF + FFc*Ec)
#define WT_LAYER   (WT_W2_OFF + Ec*FFc)

// ---------------- scratch ----------------
__device__ __half g_h   [(size_t)ROWS*Ec];
__device__ __half g_qkv [(size_t)ROWS*QKVN];
__device__ __half g_ao  [(size_t)ROWS*Ec];
__device__ __half g_ff  [(size_t)ROWS*FFc];
__device__ __half g_wt  [(size_t)Lc*WT_LAYER];

// ---------------- helpers ----------------
__device__ __forceinline__ uint32_t smem_u32(const void* p) {
    uint32_t a;
    asm("{ .reg .u64 t; cvta.to.shared.u64 t, %1; cvt.u32.u64 %0, t; }" : "=r"(a) : "l"(p));
    return a;
}
#define SW128(x) ((x) ^ (((x) >> 3) & 0x70))

#define CP16(dst, src) \
    asm volatile("cp.async.cg.shared.global [%0], [%1], 16;" :: "r"(dst), "l"(src) : "memory")
#define CPCOMMIT() asm volatile("cp.async.commit_group;" ::: "memory")

__device__ __forceinline__ void ldmx4(uint32_t& r0, uint32_t& r1, uint32_t& r2, uint32_t& r3,
                                      uint32_t addr) {
    asm volatile("ldmatrix.sync.aligned.m8n8.x4.shared.b16 {%0,%1,%2,%3}, [%4];"
                 : "=r"(r0), "=r"(r1), "=r"(r2), "=r"(r3) : "r"(addr));
}
__device__ __forceinline__ void mma16816(float* c, const uint32_t* a, const uint32_t* b) {
    asm volatile("mma.sync.aligned.m16n8k16.row.col.f32.f16.f16.f32 "
                 "{%0,%1,%2,%3}, {%4,%5,%6,%7}, {%8,%9}, {%0,%1,%2,%3};"
                 : "+f"(c[0]), "+f"(c[1]), "+f"(c[2]), "+f"(c[3])
                 : "r"(a[0]), "r"(a[1]), "r"(a[2]), "r"(a[3]), "r"(b[0]), "r"(b[1]));
}

// ---------------- fused embedding + LN1(layer 0) ----------------------------
__global__ void embed_ln_kernel(const int* __restrict__ tokens,
                                const float* __restrict__ tok_emb,
                                const float* __restrict__ pos_emb,
                                const float* __restrict__ g,
                                const float* __restrict__ b,
                                float* __restrict__ x,
                                __half* __restrict__ h) {
    int warp = (blockIdx.x * blockDim.x + threadIdx.x) >> 5;
    int lane = threadIdx.x & 31;
    if (warp >= ROWS) return;
    int t   = warp & (Tc - 1);
    int tok = tokens[warp];
    const float* te = tok_emb + (size_t)tok * Ec;
    const float* pe = pos_emb + (size_t)t * Ec;
    float v[16];
    float s = 0.f;
#pragma unroll
    for (int i = 0; i < 16; i++) {
        int idx = lane + i * 32;
        v[i] = te[idx] + pe[idx];
        s += v[i];
    }
    size_t rb = (size_t)warp * Ec;
#pragma unroll
    for (int i = 0; i < 16; i++) x[rb + lane + i * 32] = v[i];
#pragma unroll
    for (int o = 16; o > 0; o >>= 1) s += __shfl_xor_sync(0xffffffffu, s, o);
    float mean = s * (1.f / Ec);
    float ss = 0.f;
#pragma unroll
    for (int i = 0; i < 16; i++) { float d = v[i] - mean; ss += d * d; }
#pragma unroll
    for (int o = 16; o > 0; o >>= 1) ss += __shfl_xor_sync(0xffffffffu, ss, o);
    float inv = rsqrtf(ss * (1.f / Ec) + EPSc);
#pragma unroll
    for (int i = 0; i < 16; i++) {
        int idx = lane + i * 32;
        h[rb + idx] = __float2half_rn((v[i] - mean) * inv * g[idx] + b[idx]);
    }
}

// ---------------- layernorm -> fp16 ----------------
__global__ void ln_kernel(const float* __restrict__ x,
                          const float* __restrict__ g,
                          const float* __restrict__ b,
                          __half* __restrict__ y) {
    int warp = (blockIdx.x * blockDim.x + threadIdx.x) >> 5;
    int lane = threadIdx.x & 31;
    if (warp >= ROWS) return;
    const float* xr = x + (size_t)warp * Ec;
    float v[16];
    float s = 0.f;
#pragma unroll
    for (int i = 0; i < 16; i++) { v[i] = xr[lane + i * 32]; s += v[i]; }
#pragma unroll
    for (int o = 16; o > 0; o >>= 1) s += __shfl_xor_sync(0xffffffffu, s, o);
    float mean = s * (1.f / Ec);
    float ss = 0.f;
#pragma unroll
    for (int i = 0; i < 16; i++) { float d = v[i] - mean; ss += d * d; }
#pragma unroll
    for (int o = 16; o > 0; o >>= 1) ss += __shfl_xor_sync(0xffffffffu, ss, o);
    float inv = rsqrtf(ss * (1.f / Ec) + EPSc);
    size_t rb = (size_t)warp * Ec;
#pragma unroll
    for (int i = 0; i < 16; i++) {
        int idx = lane + i * 32;
        y[rb + idx] = __float2half_rn((v[i] - mean) * inv * g[idx] + b[idx]);
    }
}

// ---------------- fused weight prep (fp16 transpose) ----------------
__global__ void prep_kernel(const float* __restrict__ Wq, const float* __restrict__ Wk,
                            const float* __restrict__ Wv, const float* __restrict__ Wo,
                            const float* __restrict__ W1, const float* __restrict__ W2,
                            __half* __restrict__ thi) {
    int l = blockIdx.z, y = blockIdx.y;
    int K = (y == 5) ? FFc : Ec;
    int N = (y == 4) ? FFc : Ec;
    int ntiles = N >> 5;
    int nt = blockIdx.x % ntiles;
    int kt = blockIdx.x / ntiles;
    if (kt >= (K >> 5)) return;

    const float* W; size_t doff;
    switch (y) {
        case 0: W = Wq + (size_t)l * Ec * Ec;  doff = WT_QKV_OFF;            break;
        case 1: W = Wk + (size_t)l * Ec * Ec;  doff = WT_QKV_OFF + Ec * Ec;  break;
        case 2: W = Wv + (size_t)l * Ec * Ec;  doff = WT_QKV_OFF + 2*Ec*Ec;  break;
        case 3: W = Wo + (size_t)l * Ec * Ec;  doff = WT_WO_OFF;             break;
        case 4: W = W1 + (size_t)l * Ec * FFc; doff = WT_W1_OFF;             break;
        default:W = W2 + (size_t)l * FFc * Ec; doff = WT_W2_OFF;             break;
    }
    doff += (size_t)l * WT_LAYER;

    __shared__ float tile[32][33];
    int n0 = nt * 32, k0 = kt * 32;
    int tx = threadIdx.x, ty = threadIdx.y;
#pragma unroll
    for (int i = 0; i < 32; i += 8)
        tile[ty + i][tx] = W[(size_t)(k0 + ty + i) * N + n0 + tx];
    __syncthreads();
#pragma unroll
    for (int i = 0; i < 32; i += 8) {
        float v = tile[tx][ty + i];
        thi[doff + (size_t)(n0 + ty + i) * K + k0 + tx] = __float2half_rn(v);
    }
}

// ---------------- mma.sync GEMM: CTA 128x128, warp 64x32, 2 CTAs/SM ----------
#define GBM 128
#define GBN 128
#define GBK 64
#define A_OFF   0
#define B_OFF   16384
#define GSTG    32768
#define NSTAGE  3
#define GEMM_SMEM (NSTAGE*GSTG)

__device__ __forceinline__ void load_chunk(
    uint32_t base, int tid, int rowA0, int rowB0, int k0, int K,
    const __half* __restrict__ A, const __half* __restrict__ B) {
#pragma unroll
    for (int i = tid; i < 1024; i += 256) {
        int r = i >> 3, j = i & 7;
        uint32_t sw = SW128((uint32_t)((r << 7) + (j << 4)));
        CP16(base + A_OFF + sw, A + (size_t)(rowA0 + r) * K + k0 + j * 8);
    }
#pragma unroll
    for (int i = tid; i < 1024; i += 256) {
        int r = i >> 3, j = i & 7;
        uint32_t sw = SW128((uint32_t)((r << 7) + (j << 4)));
        CP16(base + B_OFF + sw, B + (size_t)(rowB0 + r) * K + k0 + j * 8);
    }
}

template <int EPI>
__global__ __launch_bounds__(256, 2)
void mma_gemm(const __half* __restrict__ A, const __half* __restrict__ B,
              const float* __restrict__ bias, const float* __restrict__ res,
              float* __restrict__ outF, __half* __restrict__ outH,
              int N, int K) {
    extern __shared__ char smem[];
    uint32_t sb = smem_u32(smem);
    int tid = threadIdx.x, wid = tid >> 5, lane = tid & 31;

    int rowA0 = blockIdx.y * GBM;
    int rowB0 = blockIdx.x * GBN;
    int warpM0 = (wid >> 2) * 64;
    int warpN0 = (wid & 3) * 32;
    const int KC = K / GBK;

    float acc[4][4][4];
#pragma unroll
    for (int i = 0; i < 4; i++)
#pragma unroll
        for (int j = 0; j < 4; j++)
#pragma unroll
            for (int r = 0; r < 4; r++) acc[i][j][r] = 0.f;

    load_chunk(sb,        tid, rowA0, rowB0, 0,   K, A, B); CPCOMMIT();
    load_chunk(sb + GSTG, tid, rowA0, rowB0, GBK, K, A, B); CPCOMMIT();

    int mat  = lane >> 3;
    int mrow = lane & 7;
    int rsel = (mat & 1) * 8 + mrow;
    int csel = mat >> 1;

    for (int c = 0; c < KC; c++) {
        uint32_t base = sb + (uint32_t)(c % NSTAGE) * GSTG;
        if (c < KC - 1) asm volatile("cp.async.wait_group 1;" ::: "memory");
        else            asm volatile("cp.async.wait_group 0;" ::: "memory");
        __syncthreads();
        if (c + 2 < KC) {
            load_chunk(sb + (uint32_t)((c + 2) % NSTAGE) * GSTG,
                       tid, rowA0, rowB0, (c + 2) * GBK, K, A, B);
            CPCOMMIT();
        }

#pragma unroll
        for (int kk = 0; kk < 4; kk++) {
            int chunk = 2 * kk + csel;
            uint32_t ah[4][4];
#pragma unroll
            for (int mi = 0; mi < 4; mi++) {
                uint32_t sw = SW128((uint32_t)((warpM0 + mi * 16 + rsel) << 7) + (chunk << 4));
                ldmx4(ah[mi][0], ah[mi][1], ah[mi][2], ah[mi][3], base + A_OFF + sw);
            }
            uint32_t bf[4][2];
#pragma unroll
            for (int bj = 0; bj < 2; bj++) {
                uint32_t sw = SW128((uint32_t)((warpN0 + bj * 16 + rsel) << 7) + (chunk << 4));
                uint32_t r0, r1, r2, r3;
                ldmx4(r0, r1, r2, r3, base + B_OFF + sw);
                bf[2*bj][0] = r0; bf[2*bj][1] = r2; bf[2*bj+1][0] = r1; bf[2*bj+1][1] = r3;
            }
#pragma unroll
            for (int mi = 0; mi < 4; mi++)
#pragma unroll
                for (int nf = 0; nf < 4; nf++)
                    mma16816(acc[mi][nf], ah[mi], bf[nf]);
        }
    }

    int grp = lane >> 2;
    int qd  = lane & 3;
#pragma unroll
    for (int mi = 0; mi < 4; mi++) {
#pragma unroll
        for (int half = 0; half < 2; half++) {
            int m = rowA0 + warpM0 + mi * 16 + half * 8 + grp;
            size_t orow = (size_t)m * N;
#pragma unroll
            for (int nf = 0; nf < 4; nf++) {
                int n = rowB0 + warpN0 + nf * 8 + qd * 2;
                float v0 = acc[mi][nf][half * 2 + 0];
                float v1 = acc[mi][nf][half * 2 + 1];
                if (EPI == 0) {
                    __half2 hh;
                    hh.x = __float2half_rn(v0);
                    hh.y = __float2half_rn(v1);
                    *(__half2*)(outH + orow + n) = hh;
                } else if (EPI == 2) {
                    float2 rr = *(const float2*)(res + orow + n);
                    float2 vv;
                    vv.x = v0 + bias[n]     + rr.x;
                    vv.y = v1 + bias[n + 1] + rr.y;
                    *(float2*)(outF + orow + n) = vv;
                } else {
                    v0 = fmaxf(v0 + bias[n],     0.f);
                    v1 = fmaxf(v1 + bias[n + 1], 0.f);
                    __half2 hh;
                    hh.x = __float2half_rn(v0);
                    hh.y = __float2half_rn(v1);
                    *(__half2*)(outH + orow + n) = hh;
                }
            }
        }
    }
}

// ---------------- MMA-based sliding-window attention -------------------------
// Per block: (b, h, 64-token tile). S = Q[64x64] @ Khalo[96x64]^T (fp32 acc),
// band softmax -> P fp16 (zeros outside band), O = P[64x96] @ V^T[64x96]^T.
#define ATT 64
#define AHALO 96
#define SQ_OFF   0u
#define SKH_OFF  8192u        // 64*128
#define SS_OFF   0u           // fp32 S (64x100) aliases sQ+sKh after MMA1
#define SVT_OFF  25600u       // V^T: 64 dims x 272B rows
#define SP_OFF   43008u       // P: 64 tokens x 272B rows
#define ATT_SMEM 60416
#define PPITCH   272          // bytes per row (68 words -> ldmatrix conflict-free)

__global__ __launch_bounds__(256)
void attn_kernel(const __half* __restrict__ qkv,
                 const int* __restrict__ mask,
                 __half* __restrict__ ao) {
    extern __shared__ char dyn[];
    uint32_t sb = smem_u32(dyn);
    __shared__ int sM[AHALO];

    int bid  = blockIdx.x;
    int tile = bid & (Tc / ATT - 1);
    int h    = (bid >> 6) & (Hc - 1);
    int b    = bid >> 9;
    int t0   = tile * ATT;
    int tid  = threadIdx.x;
    int wid  = tid >> 5, lane = tid & 31;

    if (tid < AHALO) {
        int tc = t0 - WINc + tid;
        sM[tid] = (tc >= 0 && tc < Tc) ? mask[b * Tc + tc] : 0;
    }
    // stage Q: 64 rows x 32 half2, SW128 128B rows
    for (int i = tid; i < 64 * 32; i += 256) {
        int r = i >> 5, j = i & 31;
        uint32_t sw = SW128((uint32_t)((r << 7) + (j << 2)));
        const __half* qr = qkv + (size_t)(b * Tc + t0 + r) * QKVN + h * Dc;
        *(uint32_t*)(dyn + SQ_OFF + sw) = *(const uint32_t*)(qr + j * 2);
    }
    // stage K halo: 96 rows x 32 half2, SW128; zero out-of-range
    // stage V^T: dims-major, pitch 272B; zero out-of-range
    for (int i = tid; i < AHALO * 32; i += 256) {
        int r = i >> 5, j = i & 31;
        int tc = t0 - WINc + r;
        uint32_t kv = 0, vv = 0;
        if (tc >= 0 && tc < Tc) {
            const __half* kr = qkv + (size_t)(b * Tc + tc) * QKVN + Ec + h * Dc;
            const __half* vr = qkv + (size_t)(b * Tc + tc) * QKVN + 2 * Ec + h * Dc;
            kv = *(const uint32_t*)(kr + j * 2);
            vv = *(const uint32_t*)(vr + j * 2);
        }
        uint32_t sw = SW128((uint32_t)((r << 7) + (j << 2)));
        *(uint32_t*)(dyn + SKH_OFF + sw) = kv;
        __half2 vh = *(__half2*)&vv;
        *(__half*)(dyn + SVT_OFF + (2 * j)     * PPITCH + r * 2) = vh.x;
        *(__half*)(dyn + SVT_OFF + (2 * j + 1) * PPITCH + r * 2) = vh.y;
    }
    // zero P (64 x 272B)
    for (int i = tid; i < 64 * PPITCH / 4; i += 256)
        ((uint32_t*)(dyn + SP_OFF))[i] = 0u;
    __syncthreads();

    int mat  = lane >> 3;
    int mrow = lane & 7;
    int rsel = (mat & 1) * 8 + mrow;
    int csel = mat >> 1;
    int grp  = lane >> 2;
    int qd   = lane & 3;

    int m0  = (wid >> 1) * 16;       // token rows (4-way M split)
    int n0k = (wid & 1) * 48;        // key cols  (2-way N split)

    // ---- MMA1: S = Q @ Khalo^T ----
    float acc1[6][4];
#pragma unroll
    for (int j = 0; j < 6; j++)
#pragma unroll
        for (int r = 0; r < 4; r++) acc1[j][r] = 0.f;
#pragma unroll
    for (int kk = 0; kk < 4; kk++) {
        int chunk = 2 * kk + csel;
        uint32_t aq[4];
        {
            uint32_t sw = SW128((uint32_t)((m0 + rsel) << 7) + (chunk << 4));
            ldmx4(aq[0], aq[1], aq[2], aq[3], sb + SQ_OFF + sw);
        }
        uint32_t bk[6][2];
#pragma unroll
        for (int bj = 0; bj < 3; bj++) {
            uint32_t sw = SW128((uint32_t)((n0k + bj * 16 + rsel) << 7) + (chunk << 4));
            uint32_t r0, r1, r2, r3;
            ldmx4(r0, r1, r2, r3, sb + SKH_OFF + sw);
            bk[2*bj][0] = r0; bk[2*bj][1] = r2; bk[2*bj+1][0] = r1; bk[2*bj+1][1] = r3;
        }
#pragma unroll
        for (int nf = 0; nf < 6; nf++)
            mma16816(acc1[nf], aq, bk[nf]);
    }
    __syncthreads();   // all ldmatrix on sQ/sKh done; safe to alias with sS

    // write S (scaled) to fp32 smem, pitch 100 floats
    float* sS = (float*)(dyn + SS_OFF);
#pragma unroll
    for (int nf = 0; nf < 6; nf++) {
        int n = n0k + nf * 8 + qd * 2;
#pragma unroll
        for (int hf = 0; hf < 2; hf++) {
            int m = m0 + hf * 8 + grp;
            float2 v;
            v.x = acc1[nf][hf * 2 + 0] * 0.125f;
            v.y = acc1[nf][hf * 2 + 1] * 0.125f;
            *(float2*)(sS + m * 100 + n) = v;
        }
    }
    __syncthreads();

    // ---- band softmax: warp per token ----
    for (int tt = wid; tt < ATT; tt += 8) {
        const float* srow = sS + tt * 100 + tt;   // band starts at halo idx tt
        float s   = (sM[tt + lane] > 0) ? srow[lane] : -1e9f;
        float s32 = (sM[tt + 32]   > 0) ? srow[32]   : -1e9f;
        float m = s;
#pragma unroll
        for (int o = 16; o > 0; o >>= 1) m = fmaxf(m, __shfl_xor_sync(0xffffffffu, m, o));
        m = fmaxf(m, s32);
        float e  = __expf(s - m);
        float es = e;
#pragma unroll
        for (int o = 16; o > 0; o >>= 1) es += __shfl_xor_sync(0xffffffffu, es, o);
        float e32 = __expf(s32 - m);
        float inv = 1.f / (es + e32);
        __half* prow = (__half*)(dyn + SP_OFF + tt * PPITCH);
        prow[tt + lane] = __float2half_rn(e * inv);
        if (lane == 0) prow[tt + 32] = __float2half_rn(e32 * inv);
    }
    __syncthreads();

    // ---- MMA2: O = P @ V^T^T  (A=P rows=tokens, B=V^T rows=dims) ----
    int n0d = (wid & 1) * 32;        // dim cols (2-way N split)
    float acc2[4][4];
#pragma unroll
    for (int j = 0; j < 4; j++)
#pragma unroll
        for (int r = 0; r < 4; r++) acc2[j][r] = 0.f;
#pragma unroll
    for (int kk = 0; kk < 6; kk++) {
        uint32_t ap[4];
        {
            uint32_t ad = sb + SP_OFF + (uint32_t)((m0 + rsel) * PPITCH + kk * 32 + csel * 16);
            ldmx4(ap[0], ap[1], ap[2], ap[3], ad);
        }
        uint32_t bv[4][2];
#pragma unroll
        for (int bj = 0; bj < 2; bj++) {
            uint32_t ad = sb + SVT_OFF + (uint32_t)((n0d + bj * 16 + rsel) * PPITCH + kk * 32 + csel * 16);
            uint32_t r0, r1, r2, r3;
            ldmx4(r0, r1, r2, r3, ad);
            bv[2*bj][0] = r0; bv[2*bj][1] = r2; bv[2*bj+1][0] = r1; bv[2*bj+1][1] = r3;
        }
#pragma unroll
        for (int nf = 0; nf < 4; nf++)
            mma16816(acc2[nf], ap, bv[nf]);
    }

    // epilogue: write ao
#pragma unroll
    for (int nf = 0; nf < 4; nf++) {
        int n = n0d + nf * 8 + qd * 2;
#pragma unroll
        for (int hf = 0; hf < 2; hf++) {
            int m = m0 + hf * 8 + grp;
            __half2 oh;
            oh.x = __float2half_rn(acc2[nf][hf * 2 + 0]);
            oh.y = __float2half_rn(acc2[nf][hf * 2 + 1]);
            *(__half2*)(ao + (size_t)(b * Tc + t0 + m) * Ec + h * Dc + n) = oh;
        }
    }
}

// ---------------- orchestration ----------------
extern "C" void kernel_launch(void* const* d_in, const int* in_sizes, int n_in,
                              void* d_out, int out_size) {
    const int*   tokens  = (const int*)  d_in[0];
    const int*   attmask = (const int*)  d_in[1];
    const float* tok_emb = (const float*)d_in[2];
    const float* pos_emb = (const float*)d_in[3];
    const float* Wq      = (const float*)d_in[4];
    const float* Wk      = (const float*)d_in[5];
    const float* Wv      = (const float*)d_in[6];
    const float* Wo      = (const float*)d_in[7];
    const float* bo      = (const float*)d_in[8];
    const float* ln1_g   = (const float*)d_in[9];
    const float* ln1_b   = (const float*)d_in[10];
    const float* ln2_g   = (const float*)d_in[11];
    const float* ln2_b   = (const float*)d_in[12];
    const float* W1      = (const float*)d_in[13];
    const float* b1      = (const float*)d_in[14];
    const float* W2      = (const float*)d_in[15];
    const float* b2      = (const float*)d_in[16];

    float* x = (float*)d_out;

    __half *h, *qkv, *ao, *ff, *wt;
    cudaGetSymbolAddress((void**)&h,   g_h);
    cudaGetSymbolAddress((void**)&qkv, g_qkv);
    cudaGetSymbolAddress((void**)&ao,  g_ao);
    cudaGetSymbolAddress((void**)&ff,  g_ff);
    cudaGetSymbolAddress((void**)&wt,  g_wt);

    cudaFuncSetAttribute(mma_gemm<0>, cudaFuncAttributeMaxDynamicSharedMemorySize, GEMM_SMEM);
    cudaFuncSetAttribute(mma_gemm<1>, cudaFuncAttributeMaxDynamicSharedMemorySize, GEMM_SMEM);
    cudaFuncSetAttribute(mma_gemm<2>, cudaFuncAttributeMaxDynamicSharedMemorySize, GEMM_SMEM);
    cudaFuncSetAttribute(attn_kernel, cudaFuncAttributeMaxDynamicSharedMemorySize, ATT_SMEM);

    prep_kernel<<<dim3(1024, 6, Lc), dim3(32, 8)>>>(Wq, Wk, Wv, Wo, W1, W2, wt);
    embed_ln_kernel<<<1024, 256>>>(tokens, tok_emb, pos_emb, ln1_g, ln1_b, x, h);

    for (int l = 0; l < Lc; l++) {
        const __half* w = wt + (size_t)l * WT_LAYER;

        if (l > 0)
            ln_kernel<<<1024, 256>>>(x, ln1_g + l * Ec, ln1_b + l * Ec, h);

        mma_gemm<0><<<dim3(QKVN / GBN, ROWS / GBM), 256, GEMM_SMEM>>>(
            h, w + WT_QKV_OFF, nullptr, nullptr, nullptr, qkv, QKVN, Ec);

        attn_kernel<<<Bc * Hc * (Tc / ATT), 256, ATT_SMEM>>>(qkv, attmask, ao);

        mma_gemm<2><<<dim3(Ec / GBN, ROWS / GBM), 256, GEMM_SMEM>>>(
            ao, w + WT_WO_OFF, bo + l * Ec, x, x, nullptr, Ec, Ec);

        ln_kernel<<<1024, 256>>>(x, ln2_g + l * Ec, ln2_b + l * Ec, h);

        mma_gemm<1><<<dim3(FFc / GBN, ROWS / GBM), 256, GEMM_SMEM>>>(
            h, w + WT_W1_OFF, b1 + l * FFc, nullptr, nullptr, ff, FFc, Ec);

        mma_gemm<2><<<dim3(Ec / GBN, ROWS / GBM), 256, GEMM_SMEM>>>(
            ff, w + WT_W2_OFF, b2 + l * Ec, x, x, nullptr, Ec, FFc);
    }
    (void)in_sizes; (void)n_in; (void)out_size;
}

// round 16
// speedup vs baseline: 1.1004x; 1.0343x over previous
#include <cuda_runtime.h>
#include <cuda_fp16.h>
#include <cstdint>

// ---------------- problem constants ----------------
#define Bc   2
#define Tc   4096
#define Ec   512
#define Hc   8
#define Dc   64
#define FFc  2048
#define Lc   2
#define WINc 16
#define NW   33
#define ROWS (Bc*Tc)      // 8192
#define EPSc 1e-5f
#define QKVN (3*Ec)       // 1536

#define WT_QKV_OFF 0
#define WT_WO_OFF  (3*Ec*Ec)
#define WT_W1_OFF  (4*Ec*Ec)
#define WT_W2_OFF  (WT_W1_OFF + FFc*Ec)
#define WT_LAYER   (WT_W2_OFF + Ec*FFc)

// ---------------- scratch ----------------
__device__ __half g_h   [(size_t)ROWS*Ec];
__device__ __half g_qkv [(size_t)ROWS*QKVN];
__device__ __half g_ao  [(size_t)ROWS*Ec];
__device__ __half g_ff  [(size_t)ROWS*FFc];
__device__ __half g_wt  [(size_t)Lc*WT_LAYER];

// ---------------- helpers ----------------
__device__ __forceinline__ uint32_t smem_u32(const void* p) {
    uint32_t a;
    asm("{ .reg .u64 t; cvta.to.shared.u64 t, %1; cvt.u32.u64 %0, t; }" : "=r"(a) : "l"(p));
    return a;
}
#define SW128(x) ((x) ^ (((x) >> 3) & 0x70))

#define CP16(dst, src) \
    asm volatile("cp.async.cg.shared.global [%0], [%1], 16;" :: "r"(dst), "l"(src) : "memory")
#define CPCOMMIT() asm volatile("cp.async.commit_group;" ::: "memory")

__device__ __forceinline__ void ldmx4(uint32_t& r0, uint32_t& r1, uint32_t& r2, uint32_t& r3,
                                      uint32_t addr) {
    asm volatile("ldmatrix.sync.aligned.m8n8.x4.shared.b16 {%0,%1,%2,%3}, [%4];"
                 : "=r"(r0), "=r"(r1), "=r"(r2), "=r"(r3) : "r"(addr));
}
__device__ __forceinline__ void mma16816(float* c, const uint32_t* a, const uint32_t* b) {
    asm volatile("mma.sync.aligned.m16n8k16.row.col.f32.f16.f16.f32 "
                 "{%0,%1,%2,%3}, {%4,%5,%6,%7}, {%8,%9}, {%0,%1,%2,%3};"
                 : "+f"(c[0]), "+f"(c[1]), "+f"(c[2]), "+f"(c[3])
                 : "r"(a[0]), "r"(a[1]), "r"(a[2]), "r"(a[3]), "r"(b[0]), "r"(b[1]));
}

// ---------------- fused embedding + LN1(layer 0) ----------------------------
__global__ void embed_ln_kernel(const int* __restrict__ tokens,
                                const float* __restrict__ tok_emb,
                                const float* __restrict__ pos_emb,
                                const float* __restrict__ g,
                                const float* __restrict__ b,
                                float* __restrict__ x,
                                __half* __restrict__ h) {
    int warp = (blockIdx.x * blockDim.x + threadIdx.x) >> 5;
    int lane = threadIdx.x & 31;
    if (warp >= ROWS) return;
    int t   = warp & (Tc - 1);
    int tok = tokens[warp];
    const float* te = tok_emb + (size_t)tok * Ec;
    const float* pe = pos_emb + (size_t)t * Ec;
    float v[16];
    float s = 0.f;
#pragma unroll
    for (int i = 0; i < 16; i++) {
        int idx = lane + i * 32;
        v[i] = te[idx] + pe[idx];
        s += v[i];
    }
    size_t rb = (size_t)warp * Ec;
#pragma unroll
    for (int i = 0; i < 16; i++) x[rb + lane + i * 32] = v[i];
#pragma unroll
    for (int o = 16; o > 0; o >>= 1) s += __shfl_xor_sync(0xffffffffu, s, o);
    float mean = s * (1.f / Ec);
    float ss = 0.f;
#pragma unroll
    for (int i = 0; i < 16; i++) { float d = v[i] - mean; ss += d * d; }
#pragma unroll
    for (int o = 16; o > 0; o >>= 1) ss += __shfl_xor_sync(0xffffffffu, ss, o);
    float inv = rsqrtf(ss * (1.f / Ec) + EPSc);
#pragma unroll
    for (int i = 0; i < 16; i++) {
        int idx = lane + i * 32;
        h[rb + idx] = __float2half_rn((v[i] - mean) * inv * g[idx] + b[idx]);
    }
}

// ---------------- layernorm -> fp16 ----------------
__global__ void ln_kernel(const float* __restrict__ x,
                          const float* __restrict__ g,
                          const float* __restrict__ b,
                          __half* __restrict__ y) {
    int warp = (blockIdx.x * blockDim.x + threadIdx.x) >> 5;
    int lane = threadIdx.x & 31;
    if (warp >= ROWS) return;
    const float* xr = x + (size_t)warp * Ec;
    float v[16];
    float s = 0.f;
#pragma unroll
    for (int i = 0; i < 16; i++) { v[i] = xr[lane + i * 32]; s += v[i]; }
#pragma unroll
    for (int o = 16; o > 0; o >>= 1) s += __shfl_xor_sync(0xffffffffu, s, o);
    float mean = s * (1.f / Ec);
    float ss = 0.f;
#pragma unroll
    for (int i = 0; i < 16; i++) { float d = v[i] - mean; ss += d * d; }
#pragma unroll
    for (int o = 16; o > 0; o >>= 1) ss += __shfl_xor_sync(0xffffffffu, ss, o);
    float inv = rsqrtf(ss * (1.f / Ec) + EPSc);
    size_t rb = (size_t)warp * Ec;
#pragma unroll
    for (int i = 0; i < 16; i++) {
        int idx = lane + i * 32;
        y[rb + idx] = __float2half_rn((v[i] - mean) * inv * g[idx] + b[idx]);
    }
}

// ---------------- fused weight prep (fp16 transpose) ----------------
__global__ void prep_kernel(const float* __restrict__ Wq, const float* __restrict__ Wk,
                            const float* __restrict__ Wv, const float* __restrict__ Wo,
                            const float* __restrict__ W1, const float* __restrict__ W2,
                            __half* __restrict__ thi) {
    int l = blockIdx.z, y = blockIdx.y;
    int K = (y == 5) ? FFc : Ec;
    int N = (y == 4) ? FFc : Ec;
    int ntiles = N >> 5;
    int nt = blockIdx.x % ntiles;
    int kt = blockIdx.x / ntiles;
    if (kt >= (K >> 5)) return;

    const float* W; size_t doff;
    switch (y) {
        case 0: W = Wq + (size_t)l * Ec * Ec;  doff = WT_QKV_OFF;            break;
        case 1: W = Wk + (size_t)l * Ec * Ec;  doff = WT_QKV_OFF + Ec * Ec;  break;
        case 2: W = Wv + (size_t)l * Ec * Ec;  doff = WT_QKV_OFF + 2*Ec*Ec;  break;
        case 3: W = Wo + (size_t)l * Ec * Ec;  doff = WT_WO_OFF;             break;
        case 4: W = W1 + (size_t)l * Ec * FFc; doff = WT_W1_OFF;             break;
        default:W = W2 + (size_t)l * FFc * Ec; doff = WT_W2_OFF;             break;
    }
    doff += (size_t)l * WT_LAYER;

    __shared__ float tile[32][33];
    int n0 = nt * 32, k0 = kt * 32;
    int tx = threadIdx.x, ty = threadIdx.y;
#pragma unroll
    for (int i = 0; i < 32; i += 8)
        tile[ty + i][tx] = W[(size_t)(k0 + ty + i) * N + n0 + tx];
    __syncthreads();
#pragma unroll
    for (int i = 0; i < 32; i += 8) {
        float v = tile[tx][ty + i];
        thi[doff + (size_t)(n0 + ty + i) * K + k0 + tx] = __float2half_rn(v);
    }
}

// ---------------- mma.sync GEMM: CTA 128x128, warp 64x32, 2 CTAs/SM ----------
#define GBM 128
#define GBN 128
#define GBK 64
#define A_OFF   0
#define B_OFF   16384
#define GSTG    32768
#define NSTAGE  3
#define GEMM_SMEM (NSTAGE*GSTG)

__device__ __forceinline__ void load_chunk(
    uint32_t base, int tid, int rowA0, int rowB0, int k0, int K,
    const __half* __restrict__ A, const __half* __restrict__ B) {
#pragma unroll
    for (int i = tid; i < 1024; i += 256) {
        int r = i >> 3, j = i & 7;
        uint32_t sw = SW128((uint32_t)((r << 7) + (j << 4)));
        CP16(base + A_OFF + sw, A + (size_t)(rowA0 + r) * K + k0 + j * 8);
    }
#pragma unroll
    for (int i = tid; i < 1024; i += 256) {
        int r = i >> 3, j = i & 7;
        uint32_t sw = SW128((uint32_t)((r << 7) + (j << 4)));
        CP16(base + B_OFF + sw, B + (size_t)(rowB0 + r) * K + k0 + j * 8);
    }
}

template <int EPI>
__global__ __launch_bounds__(256, 2)
void mma_gemm(const __half* __restrict__ A, const __half* __restrict__ B,
              const float* __restrict__ bias, const float* __restrict__ res,
              float* __restrict__ outF, __half* __restrict__ outH,
              int N, int K) {
    extern __shared__ char smem[];
    uint32_t sb = smem_u32(smem);
    int tid = threadIdx.x, wid = tid >> 5, lane = tid & 31;

    int rowA0 = blockIdx.y * GBM;
    int rowB0 = blockIdx.x * GBN;
    int warpM0 = (wid >> 2) * 64;
    int warpN0 = (wid & 3) * 32;
    const int KC = K / GBK;

    float acc[4][4][4];
#pragma unroll
    for (int i = 0; i < 4; i++)
#pragma unroll
        for (int j = 0; j < 4; j++)
#pragma unroll
            for (int r = 0; r < 4; r++) acc[i][j][r] = 0.f;

    load_chunk(sb,        tid, rowA0, rowB0, 0,   K, A, B); CPCOMMIT();
    load_chunk(sb + GSTG, tid, rowA0, rowB0, GBK, K, A, B); CPCOMMIT();

    int mat  = lane >> 3;
    int mrow = lane & 7;
    int rsel = (mat & 1) * 8 + mrow;
    int csel = mat >> 1;

    for (int c = 0; c < KC; c++) {
        uint32_t base = sb + (uint32_t)(c % NSTAGE) * GSTG;
        if (c < KC - 1) asm volatile("cp.async.wait_group 1;" ::: "memory");
        else            asm volatile("cp.async.wait_group 0;" ::: "memory");
        __syncthreads();
        if (c + 2 < KC) {
            load_chunk(sb + (uint32_t)((c + 2) % NSTAGE) * GSTG,
                       tid, rowA0, rowB0, (c + 2) * GBK, K, A, B);
            CPCOMMIT();
        }

#pragma unroll
        for (int kk = 0; kk < 4; kk++) {
            int chunk = 2 * kk + csel;
            uint32_t ah[4][4];
#pragma unroll
            for (int mi = 0; mi < 4; mi++) {
                uint32_t sw = SW128((uint32_t)((warpM0 + mi * 16 + rsel) << 7) + (chunk << 4));
                ldmx4(ah[mi][0], ah[mi][1], ah[mi][2], ah[mi][3], base + A_OFF + sw);
            }
            uint32_t bf[4][2];
#pragma unroll
            for (int bj = 0; bj < 2; bj++) {
                uint32_t sw = SW128((uint32_t)((warpN0 + bj * 16 + rsel) << 7) + (chunk << 4));
                uint32_t r0, r1, r2, r3;
                ldmx4(r0, r1, r2, r3, base + B_OFF + sw);
                bf[2*bj][0] = r0; bf[2*bj][1] = r2; bf[2*bj+1][0] = r1; bf[2*bj+1][1] = r3;
            }
#pragma unroll
            for (int mi = 0; mi < 4; mi++)
#pragma unroll
                for (int nf = 0; nf < 4; nf++)
                    mma16816(acc[mi][nf], ah[mi], bf[nf]);
        }
    }

    int grp = lane >> 2;
    int qd  = lane & 3;
#pragma unroll
    for (int mi = 0; mi < 4; mi++) {
#pragma unroll
        for (int half = 0; half < 2; half++) {
            int m = rowA0 + warpM0 + mi * 16 + half * 8 + grp;
            size_t orow = (size_t)m * N;
#pragma unroll
            for (int nf = 0; nf < 4; nf++) {
                int n = rowB0 + warpN0 + nf * 8 + qd * 2;
                float v0 = acc[mi][nf][half * 2 + 0];
                float v1 = acc[mi][nf][half * 2 + 1];
                if (EPI == 0) {
                    __half2 hh;
                    hh.x = __float2half_rn(v0);
                    hh.y = __float2half_rn(v1);
                    *(__half2*)(outH + orow + n) = hh;
                } else if (EPI == 2) {
                    float2 rr = *(const float2*)(res + orow + n);
                    float2 vv;
                    vv.x = v0 + bias[n]     + rr.x;
                    vv.y = v1 + bias[n + 1] + rr.y;
                    *(float2*)(outF + orow + n) = vv;
                } else {
                    v0 = fmaxf(v0 + bias[n],     0.f);
                    v1 = fmaxf(v1 + bias[n + 1], 0.f);
                    __half2 hh;
                    hh.x = __float2half_rn(v0);
                    hh.y = __float2half_rn(v1);
                    *(__half2*)(outH + orow + n) = hh;
                }
            }
        }
    }
}

// ---------------- MMA attention, band-restricted + windowed S/P --------------
// Warp pair (wid>>1) owns token group [m0, m0+16). S computed only over window
// [m0, m0+64) of the (zero-padded) 112-key halo; softmax band [tt, tt+33)
// always inside window; P zeros gate the out-of-band keys in MMA2.
#define ATT 64
#define AHALO 112            // 96 real + 16 pad so window m0+64 <= 112
#define SQ_OFF   0u
#define SKH_OFF  8192u       // 112*128 = 14336
#define SS_OFF   0u          // fp32 S windowed 64x68 floats = 17408 (alias Q/Kh)
#define SVT_OFF  22528u      // V^T: 64 dims x 240B = 15360
#define SP_OFF   37888u      // P windowed: 64 rows x 144B = 9216
#define ATT_SMEM 47104
#define VPITCH   240         // 60 words: ldmatrix rows -> distinct bank groups
#define PPITCH   144         // 36 words: ldmatrix rows -> distinct bank groups

__global__ __launch_bounds__(256)
void attn_kernel(const __half* __restrict__ qkv,
                 const int* __restrict__ mask,
                 __half* __restrict__ ao) {
    extern __shared__ char dyn[];
    uint32_t sb = smem_u32(dyn);
    __shared__ int sM[AHALO];

    int bid  = blockIdx.x;
    int tile = bid & (Tc / ATT - 1);
    int h    = (bid >> 6) & (Hc - 1);
    int b    = bid >> 9;
    int t0   = tile * ATT;
    int tid  = threadIdx.x;
    int wid  = tid >> 5, lane = tid & 31;

    if (tid < AHALO) {
        int tc = t0 - WINc + tid;
        sM[tid] = (tc >= 0 && tc < Tc) ? mask[b * Tc + tc] : 0;
    }
    // stage Q (64 x 128B SW128)
    for (int i = tid; i < 64 * 32; i += 256) {
        int r = i >> 5, j = i & 31;
        uint32_t sw = SW128((uint32_t)((r << 7) + (j << 2)));
        const __half* qr = qkv + (size_t)(b * Tc + t0 + r) * QKVN + h * Dc;
        *(uint32_t*)(dyn + SQ_OFF + sw) = *(const uint32_t*)(qr + j * 2);
    }
    // stage K halo (112 x 128B SW128, zero pad) + V^T (dims x keys, 240B pitch)
    for (int i = tid; i < AHALO * 32; i += 256) {
        int r = i >> 5, j = i & 31;
        int tc = t0 - WINc + r;
        uint32_t kv = 0, vv = 0;
        if (tc >= 0 && tc < Tc) {
            const __half* kr = qkv + (size_t)(b * Tc + tc) * QKVN + Ec + h * Dc;
            const __half* vr = qkv + (size_t)(b * Tc + tc) * QKVN + 2 * Ec + h * Dc;
            kv = *(const uint32_t*)(kr + j * 2);
            vv = *(const uint32_t*)(vr + j * 2);
        }
        uint32_t sw = SW128((uint32_t)((r << 7) + (j << 2)));
        *(uint32_t*)(dyn + SKH_OFF + sw) = kv;
        __half2 vh = *(__half2*)&vv;
        *(__half*)(dyn + SVT_OFF + (2 * j)     * VPITCH + r * 2) = vh.x;
        *(__half*)(dyn + SVT_OFF + (2 * j + 1) * VPITCH + r * 2) = vh.y;
    }
    // zero windowed P (64 x 144B)
    for (int i = tid; i < 64 * PPITCH / 4; i += 256)
        ((uint32_t*)(dyn + SP_OFF))[i] = 0u;
    __syncthreads();

    int mat  = lane >> 3;
    int mrow = lane & 7;
    int rsel = (mat & 1) * 8 + mrow;
    int csel = mat >> 1;
    int grp  = lane >> 2;
    int qd   = lane & 3;

    int m0  = (wid >> 1) * 16;                  // token group
    int nw0 = (wid & 1) * 32;                   // window-col sub-split

    // ---- MMA1: S[m0..m0+16) x window [m0, m0+64) (this warp: 32 cols) ----
    float acc1[4][4];
#pragma unroll
    for (int j = 0; j < 4; j++)
#pragma unroll
        for (int r = 0; r < 4; r++) acc1[j][r] = 0.f;
#pragma unroll
    for (int kk = 0; kk < 4; kk++) {
        int chunk = 2 * kk + csel;
        uint32_t aq[4];
        {
            uint32_t sw = SW128((uint32_t)((m0 + rsel) << 7) + (chunk << 4));
            ldmx4(aq[0], aq[1], aq[2], aq[3], sb + SQ_OFF + sw);
        }
        uint32_t bk[4][2];
#pragma unroll
        for (int bj = 0; bj < 2; bj++) {
            int krow = m0 + nw0 + bj * 16 + rsel;   // halo row < 112
            uint32_t sw = SW128((uint32_t)(krow << 7) + (chunk << 4));
            uint32_t r0, r1, r2, r3;
            ldmx4(r0, r1, r2, r3, sb + SKH_OFF + sw);
            bk[2*bj][0] = r0; bk[2*bj][1] = r2; bk[2*bj+1][0] = r1; bk[2*bj+1][1] = r3;
        }
#pragma unroll
        for (int nf = 0; nf < 4; nf++)
            mma16816(acc1[nf], aq, bk[nf]);
    }
    __syncthreads();   // Q/Kh ldmatrix complete -> safe to alias with S

    // write windowed S (scaled), pitch 68 floats; col = window-local
    float* sS = (float*)(dyn + SS_OFF);
#pragma unroll
    for (int nf = 0; nf < 4; nf++) {
        int n = nw0 + nf * 8 + qd * 2;
#pragma unroll
        for (int hf = 0; hf < 2; hf++) {
            int m = m0 + hf * 8 + grp;
            float2 v;
            v.x = acc1[nf][hf * 2 + 0] * 0.125f;
            v.y = acc1[nf][hf * 2 + 1] * 0.125f;
            *(float2*)(sS + m * 68 + n) = v;
        }
    }
    __syncthreads();

    // ---- band softmax: warp per token; window-local band starts at tt&15 ----
    for (int tt = wid; tt < ATT; tt += 8) {
        int wl = tt & 15;                       // tt - m0(group)
        const float* srow = sS + tt * 68 + wl;
        float s   = (sM[tt + lane] > 0) ? srow[lane] : -1e9f;
        float s32 = (sM[tt + 32]   > 0) ? srow[32]   : -1e9f;
        float m = s;
#pragma unroll
        for (int o = 16; o > 0; o >>= 1) m = fmaxf(m, __shfl_xor_sync(0xffffffffu, m, o));
        m = fmaxf(m, s32);
        float e  = __expf(s - m);
        float es = e;
#pragma unroll
        for (int o = 16; o > 0; o >>= 1) es += __shfl_xor_sync(0xffffffffu, es, o);
        float e32 = __expf(s32 - m);
        float inv = 1.f / (es + e32);
        __half* prow = (__half*)(dyn + SP_OFF + tt * PPITCH);
        prow[wl + lane] = __float2half_rn(e * inv);
        if (lane == 0) prow[wl + 32] = __float2half_rn(e32 * inv);
    }
    __syncthreads();

    // ---- MMA2: O = P_window @ Vt_window^T (4 window chunks) ----
    int n0d = (wid & 1) * 32;
    float acc2[4][4];
#pragma unroll
    for (int j = 0; j < 4; j++)
#pragma unroll
        for (int r = 0; r < 4; r++) acc2[j][r] = 0.f;
#pragma unroll
    for (int kk = 0; kk < 4; kk++) {
        uint32_t ap[4];
        {
            uint32_t ad = sb + SP_OFF + (uint32_t)((m0 + rsel) * PPITCH + kk * 32 + csel * 16);
            ldmx4(ap[0], ap[1], ap[2], ap[3], ad);
        }
        uint32_t bv[4][2];
#pragma unroll
        for (int bj = 0; bj < 2; bj++) {
            uint32_t ad = sb + SVT_OFF +
                (uint32_t)((n0d + bj * 16 + rsel) * VPITCH + m0 * 2 + kk * 32 + csel * 16);
            uint32_t r0, r1, r2, r3;
            ldmx4(r0, r1, r2, r3, ad);
            bv[2*bj][0] = r0; bv[2*bj][1] = r2; bv[2*bj+1][0] = r1; bv[2*bj+1][1] = r3;
        }
#pragma unroll
        for (int nf = 0; nf < 4; nf++)
            mma16816(acc2[nf], ap, bv[nf]);
    }

#pragma unroll
    for (int nf = 0; nf < 4; nf++) {
        int n = n0d + nf * 8 + qd * 2;
#pragma unroll
        for (int hf = 0; hf < 2; hf++) {
            int m = m0 + hf * 8 + grp;
            __half2 oh;
            oh.x = __float2half_rn(acc2[nf][hf * 2 + 0]);
            oh.y = __float2half_rn(acc2[nf][hf * 2 + 1]);
            *(__half2*)(ao + (size_t)(b * Tc + t0 + m) * Ec + h * Dc + n) = oh;
        }
    }
}

// ---------------- orchestration ----------------
extern "C" void kernel_launch(void* const* d_in, const int* in_sizes, int n_in,
                              void* d_out, int out_size) {
    const int*   tokens  = (const int*)  d_in[0];
    const int*   attmask = (const int*)  d_in[1];
    const float* tok_emb = (const float*)d_in[2];
    const float* pos_emb = (const float*)d_in[3];
    const float* Wq      = (const float*)d_in[4];
    const float* Wk      = (const float*)d_in[5];
    const float* Wv      = (const float*)d_in[6];
    const float* Wo      = (const float*)d_in[7];
    const float* bo      = (const float*)d_in[8];
    const float* ln1_g   = (const float*)d_in[9];
    const float* ln1_b   = (const float*)d_in[10];
    const float* ln2_g   = (const float*)d_in[11];
    const float* ln2_b   = (const float*)d_in[12];
    const float* W1      = (const float*)d_in[13];
    const float* b1      = (const float*)d_in[14];
    const float* W2      = (const float*)d_in[15];
    const float* b2      = (const float*)d_in[16];

    float* x = (float*)d_out;

    __half *h, *qkv, *ao, *ff, *wt;
    cudaGetSymbolAddress((void**)&h,   g_h);
    cudaGetSymbolAddress((void**)&qkv, g_qkv);
    cudaGetSymbolAddress((void**)&ao,  g_ao);
    cudaGetSymbolAddress((void**)&ff,  g_ff);
    cudaGetSymbolAddress((void**)&wt,  g_wt);

    cudaFuncSetAttribute(mma_gemm<0>, cudaFuncAttributeMaxDynamicSharedMemorySize, GEMM_SMEM);
    cudaFuncSetAttribute(mma_gemm<1>, cudaFuncAttributeMaxDynamicSharedMemorySize, GEMM_SMEM);
    cudaFuncSetAttribute(mma_gemm<2>, cudaFuncAttributeMaxDynamicSharedMemorySize, GEMM_SMEM);
    cudaFuncSetAttribute(attn_kernel, cudaFuncAttributeMaxDynamicSharedMemorySize, ATT_SMEM);

    prep_kernel<<<dim3(1024, 6, Lc), dim3(32, 8)>>>(Wq, Wk, Wv, Wo, W1, W2, wt);
    embed_ln_kernel<<<1024, 256>>>(tokens, tok_emb, pos_emb, ln1_g, ln1_b, x, h);

    for (int l = 0; l < Lc; l++) {
        const __half* w = wt + (size_t)l * WT_LAYER;

        if (l > 0)
            ln_kernel<<<1024, 256>>>(x, ln1_g + l * Ec, ln1_b + l * Ec, h);

        mma_gemm<0><<<dim3(QKVN / GBN, ROWS / GBM), 256, GEMM_SMEM>>>(
            h, w + WT_QKV_OFF, nullptr, nullptr, nullptr, qkv, QKVN, Ec);

        attn_kernel<<<Bc * Hc * (Tc / ATT), 256, ATT_SMEM>>>(qkv, attmask, ao);

        mma_gemm<2><<<dim3(Ec / GBN, ROWS / GBM), 256, GEMM_SMEM>>>(
            ao, w + WT_WO_OFF, bo + l * Ec, x, x, nullptr, Ec, Ec);

        ln_kernel<<<1024, 256>>>(x, ln2_g + l * Ec, ln2_b + l * Ec, h);

        mma_gemm<1><<<dim3(FFc / GBN, ROWS / GBM), 256, GEMM_SMEM>>>(
            h, w + WT_W1_OFF, b1 + l * FFc, nullptr, nullptr, ff, FFc, Ec);

        mma_gemm<2><<<dim3(Ec / GBN, ROWS / GBM), 256, GEMM_SMEM>>>(
            ff, w + WT_W2_OFF, b2 + l * Ec, x, x, nullptr, Ec, FFc);
    }
    (void)in_sizes; (void)n_in; (void)out_size;
}

// round 17
// speedup vs baseline: 1.1049x; 1.0041x over previous
#include <cuda_runtime.h>
#include <cuda_fp16.h>
#include <cstdint>

// ---------------- problem constants ----------------
#define Bc   2
#define Tc   4096
#define Ec   512
#define Hc   8
#define Dc   64
#define FFc  2048
#define Lc   2
#define WINc 16
#define NW   33
#define ROWS (Bc*Tc)      // 8192
#define EPSc 1e-5f
#define QKVN (3*Ec)       // 1536

#define WT_QKV_OFF 0
#define WT_WO_OFF  (3*Ec*Ec)
#define WT_W1_OFF  (4*Ec*Ec)
#define WT_W2_OFF  (WT_W1_OFF + FFc*Ec)
#define WT_LAYER   (WT_W2_OFF + Ec*FFc)

// ---------------- scratch ----------------
__device__ __half g_h   [(size_t)ROWS*Ec];
__device__ __half g_qkv [(size_t)ROWS*QKVN];
__device__ __half g_ao  [(size_t)ROWS*Ec];
__device__ __half g_ff  [(size_t)ROWS*FFc];
__device__ __half g_wt  [(size_t)Lc*WT_LAYER];

// ---------------- helpers ----------------
__device__ __forceinline__ uint32_t smem_u32(const void* p) {
    uint32_t a;
    asm("{ .reg .u64 t; cvta.to.shared.u64 t, %1; cvt.u32.u64 %0, t; }" : "=r"(a) : "l"(p));
    return a;
}
#define SW128(x) ((x) ^ (((x) >> 3) & 0x70))

#define CP16(dst, src) \
    asm volatile("cp.async.cg.shared.global [%0], [%1], 16;" :: "r"(dst), "l"(src) : "memory")
#define CPCOMMIT() asm volatile("cp.async.commit_group;" ::: "memory")

__device__ __forceinline__ void ldmx4(uint32_t& r0, uint32_t& r1, uint32_t& r2, uint32_t& r3,
                                      uint32_t addr) {
    asm volatile("ldmatrix.sync.aligned.m8n8.x4.shared.b16 {%0,%1,%2,%3}, [%4];"
                 : "=r"(r0), "=r"(r1), "=r"(r2), "=r"(r3) : "r"(addr));
}
__device__ __forceinline__ void ldmx4t(uint32_t& r0, uint32_t& r1, uint32_t& r2, uint32_t& r3,
                                       uint32_t addr) {
    asm volatile("ldmatrix.sync.aligned.m8n8.x4.trans.shared.b16 {%0,%1,%2,%3}, [%4];"
                 : "=r"(r0), "=r"(r1), "=r"(r2), "=r"(r3) : "r"(addr));
}
__device__ __forceinline__ void mma16816(float* c, const uint32_t* a, const uint32_t* b) {
    asm volatile("mma.sync.aligned.m16n8k16.row.col.f32.f16.f16.f32 "
                 "{%0,%1,%2,%3}, {%4,%5,%6,%7}, {%8,%9}, {%0,%1,%2,%3};"
                 : "+f"(c[0]), "+f"(c[1]), "+f"(c[2]), "+f"(c[3])
                 : "r"(a[0]), "r"(a[1]), "r"(a[2]), "r"(a[3]), "r"(b[0]), "r"(b[1]));
}

// ---------------- fused embedding + LN1(layer 0) ----------------------------
__global__ void embed_ln_kernel(const int* __restrict__ tokens,
                                const float* __restrict__ tok_emb,
                                const float* __restrict__ pos_emb,
                                const float* __restrict__ g,
                                const float* __restrict__ b,
                                float* __restrict__ x,
                                __half* __restrict__ h) {
    int warp = (blockIdx.x * blockDim.x + threadIdx.x) >> 5;
    int lane = threadIdx.x & 31;
    if (warp >= ROWS) return;
    int t   = warp & (Tc - 1);
    int tok = tokens[warp];
    const float* te = tok_emb + (size_t)tok * Ec;
    const float* pe = pos_emb + (size_t)t * Ec;
    float v[16];
    float s = 0.f;
#pragma unroll
    for (int i = 0; i < 16; i++) {
        int idx = lane + i * 32;
        v[i] = te[idx] + pe[idx];
        s += v[i];
    }
    size_t rb = (size_t)warp * Ec;
#pragma unroll
    for (int i = 0; i < 16; i++) x[rb + lane + i * 32] = v[i];
#pragma unroll
    for (int o = 16; o > 0; o >>= 1) s += __shfl_xor_sync(0xffffffffu, s, o);
    float mean = s * (1.f / Ec);
    float ss = 0.f;
#pragma unroll
    for (int i = 0; i < 16; i++) { float d = v[i] - mean; ss += d * d; }
#pragma unroll
    for (int o = 16; o > 0; o >>= 1) ss += __shfl_xor_sync(0xffffffffu, ss, o);
    float inv = rsqrtf(ss * (1.f / Ec) + EPSc);
#pragma unroll
    for (int i = 0; i < 16; i++) {
        int idx = lane + i * 32;
        h[rb + idx] = __float2half_rn((v[i] - mean) * inv * g[idx] + b[idx]);
    }
}

// ---------------- layernorm -> fp16 ----------------
__global__ void ln_kernel(const float* __restrict__ x,
                          const float* __restrict__ g,
                          const float* __restrict__ b,
                          __half* __restrict__ y) {
    int warp = (blockIdx.x * blockDim.x + threadIdx.x) >> 5;
    int lane = threadIdx.x & 31;
    if (warp >= ROWS) return;
    const float* xr = x + (size_t)warp * Ec;
    float v[16];
    float s = 0.f;
#pragma unroll
    for (int i = 0; i < 16; i++) { v[i] = xr[lane + i * 32]; s += v[i]; }
#pragma unroll
    for (int o = 16; o > 0; o >>= 1) s += __shfl_xor_sync(0xffffffffu, s, o);
    float mean = s * (1.f / Ec);
    float ss = 0.f;
#pragma unroll
    for (int i = 0; i < 16; i++) { float d = v[i] - mean; ss += d * d; }
#pragma unroll
    for (int o = 16; o > 0; o >>= 1) ss += __shfl_xor_sync(0xffffffffu, ss, o);
    float inv = rsqrtf(ss * (1.f / Ec) + EPSc);
    size_t rb = (size_t)warp * Ec;
#pragma unroll
    for (int i = 0; i < 16; i++) {
        int idx = lane + i * 32;
        y[rb + idx] = __float2half_rn((v[i] - mean) * inv * g[idx] + b[idx]);
    }
}

// ---------------- fused weight prep (fp16 transpose) ----------------
__global__ void prep_kernel(const float* __restrict__ Wq, const float* __restrict__ Wk,
                            const float* __restrict__ Wv, const float* __restrict__ Wo,
                            const float* __restrict__ W1, const float* __restrict__ W2,
                            __half* __restrict__ thi) {
    int l = blockIdx.z, y = blockIdx.y;
    int K = (y == 5) ? FFc : Ec;
    int N = (y == 4) ? FFc : Ec;
    int ntiles = N >> 5;
    int nt = blockIdx.x % ntiles;
    int kt = blockIdx.x / ntiles;
    if (kt >= (K >> 5)) return;

    const float* W; size_t doff;
    switch (y) {
        case 0: W = Wq + (size_t)l * Ec * Ec;  doff = WT_QKV_OFF;            break;
        case 1: W = Wk + (size_t)l * Ec * Ec;  doff = WT_QKV_OFF + Ec * Ec;  break;
        case 2: W = Wv + (size_t)l * Ec * Ec;  doff = WT_QKV_OFF + 2*Ec*Ec;  break;
        case 3: W = Wo + (size_t)l * Ec * Ec;  doff = WT_WO_OFF;             break;
        case 4: W = W1 + (size_t)l * Ec * FFc; doff = WT_W1_OFF;             break;
        default:W = W2 + (size_t)l * FFc * Ec; doff = WT_W2_OFF;             break;
    }
    doff += (size_t)l * WT_LAYER;

    __shared__ float tile[32][33];
    int n0 = nt * 32, k0 = kt * 32;
    int tx = threadIdx.x, ty = threadIdx.y;
#pragma unroll
    for (int i = 0; i < 32; i += 8)
        tile[ty + i][tx] = W[(size_t)(k0 + ty + i) * N + n0 + tx];
    __syncthreads();
#pragma unroll
    for (int i = 0; i < 32; i += 8) {
        float v = tile[tx][ty + i];
        thi[doff + (size_t)(n0 + ty + i) * K + k0 + tx] = __float2half_rn(v);
    }
}

// ---------------- mma.sync GEMM: CTA 128x128, warp 64x32, 2 CTAs/SM ----------
#define GBM 128
#define GBN 128
#define GBK 64
#define A_OFF   0
#define B_OFF   16384
#define GSTG    32768
#define NSTAGE  3
#define GEMM_SMEM (NSTAGE*GSTG)

__device__ __forceinline__ void load_chunk(
    uint32_t base, int tid, int rowA0, int rowB0, int k0, int K,
    const __half* __restrict__ A, const __half* __restrict__ B) {
#pragma unroll
    for (int i = tid; i < 1024; i += 256) {
        int r = i >> 3, j = i & 7;
        uint32_t sw = SW128((uint32_t)((r << 7) + (j << 4)));
        CP16(base + A_OFF + sw, A + (size_t)(rowA0 + r) * K + k0 + j * 8);
    }
#pragma unroll
    for (int i = tid; i < 1024; i += 256) {
        int r = i >> 3, j = i & 7;
        uint32_t sw = SW128((uint32_t)((r << 7) + (j << 4)));
        CP16(base + B_OFF + sw, B + (size_t)(rowB0 + r) * K + k0 + j * 8);
    }
}

template <int EPI>
__global__ __launch_bounds__(256, 2)
void mma_gemm(const __half* __restrict__ A, const __half* __restrict__ B,
              const float* __restrict__ bias, const float* __restrict__ res,
              float* __restrict__ outF, __half* __restrict__ outH,
              int N, int K) {
    extern __shared__ char smem[];
    uint32_t sb = smem_u32(smem);
    int tid = threadIdx.x, wid = tid >> 5, lane = tid & 31;

    int rowA0 = blockIdx.y * GBM;
    int rowB0 = blockIdx.x * GBN;
    int warpM0 = (wid >> 2) * 64;
    int warpN0 = (wid & 3) * 32;
    const int KC = K / GBK;

    float acc[4][4][4];
#pragma unroll
    for (int i = 0; i < 4; i++)
#pragma unroll
        for (int j = 0; j < 4; j++)
#pragma unroll
            for (int r = 0; r < 4; r++) acc[i][j][r] = 0.f;

    load_chunk(sb,        tid, rowA0, rowB0, 0,   K, A, B); CPCOMMIT();
    load_chunk(sb + GSTG, tid, rowA0, rowB0, GBK, K, A, B); CPCOMMIT();

    int mat  = lane >> 3;
    int mrow = lane & 7;
    int rsel = (mat & 1) * 8 + mrow;
    int csel = mat >> 1;

    for (int c = 0; c < KC; c++) {
        uint32_t base = sb + (uint32_t)(c % NSTAGE) * GSTG;
        if (c < KC - 1) asm volatile("cp.async.wait_group 1;" ::: "memory");
        else            asm volatile("cp.async.wait_group 0;" ::: "memory");
        __syncthreads();
        if (c + 2 < KC) {
            load_chunk(sb + (uint32_t)((c + 2) % NSTAGE) * GSTG,
                       tid, rowA0, rowB0, (c + 2) * GBK, K, A, B);
            CPCOMMIT();
        }

#pragma unroll
        for (int kk = 0; kk < 4; kk++) {
            int chunk = 2 * kk + csel;
            uint32_t ah[4][4];
#pragma unroll
            for (int mi = 0; mi < 4; mi++) {
                uint32_t sw = SW128((uint32_t)((warpM0 + mi * 16 + rsel) << 7) + (chunk << 4));
                ldmx4(ah[mi][0], ah[mi][1], ah[mi][2], ah[mi][3], base + A_OFF + sw);
            }
            uint32_t bf[4][2];
#pragma unroll
            for (int bj = 0; bj < 2; bj++) {
                uint32_t sw = SW128((uint32_t)((warpN0 + bj * 16 + rsel) << 7) + (chunk << 4));
                uint32_t r0, r1, r2, r3;
                ldmx4(r0, r1, r2, r3, base + B_OFF + sw);
                bf[2*bj][0] = r0; bf[2*bj][1] = r2; bf[2*bj+1][0] = r1; bf[2*bj+1][1] = r3;
            }
#pragma unroll
            for (int mi = 0; mi < 4; mi++)
#pragma unroll
                for (int nf = 0; nf < 4; nf++)
                    mma16816(acc[mi][nf], ah[mi], bf[nf]);
        }
    }

    int grp = lane >> 2;
    int qd  = lane & 3;
#pragma unroll
    for (int mi = 0; mi < 4; mi++) {
#pragma unroll
        for (int half = 0; half < 2; half++) {
            int m = rowA0 + warpM0 + mi * 16 + half * 8 + grp;
            size_t orow = (size_t)m * N;
#pragma unroll
            for (int nf = 0; nf < 4; nf++) {
                int n = rowB0 + warpN0 + nf * 8 + qd * 2;
                float v0 = acc[mi][nf][half * 2 + 0];
                float v1 = acc[mi][nf][half * 2 + 1];
                if (EPI == 0) {
                    __half2 hh;
                    hh.x = __float2half_rn(v0);
                    hh.y = __float2half_rn(v1);
                    *(__half2*)(outH + orow + n) = hh;
                } else if (EPI == 2) {
                    float2 rr = *(const float2*)(res + orow + n);
                    float2 vv;
                    vv.x = v0 + bias[n]     + rr.x;
                    vv.y = v1 + bias[n + 1] + rr.y;
                    *(float2*)(outF + orow + n) = vv;
                } else {
                    v0 = fmaxf(v0 + bias[n],     0.f);
                    v1 = fmaxf(v1 + bias[n + 1], 0.f);
                    __half2 hh;
                    hh.x = __float2half_rn(v0);
                    hh.y = __float2half_rn(v1);
                    *(__half2*)(outH + orow + n) = hh;
                }
            }
        }
    }
}

// ---------------- MMA attention: band-restricted, V via ldmatrix.trans -------
#define ATT 64
#define AHALO 112            // 96 real + 16 pad so window m0+64 <= 112
#define SQ_OFF   0u
#define SKH_OFF  8192u       // 112*128 = 14336
#define SS_OFF   0u          // fp32 S windowed 64x68 floats = 17408 (alias Q/Kh)
#define SVH_OFF  22528u      // V rows, SW128: 112*128 = 14336
#define SP_OFF   36864u      // P windowed: 64 rows x 144B = 9216
#define ATT_SMEM 46080
#define PPITCH   144         // 36 words: ldmatrix rows -> distinct bank groups

__global__ __launch_bounds__(256)
void attn_kernel(const __half* __restrict__ qkv,
                 const int* __restrict__ mask,
                 __half* __restrict__ ao) {
    extern __shared__ char dyn[];
    uint32_t sb = smem_u32(dyn);
    __shared__ int sM[AHALO];

    int bid  = blockIdx.x;
    int tile = bid & (Tc / ATT - 1);
    int h    = (bid >> 6) & (Hc - 1);
    int b    = bid >> 9;
    int t0   = tile * ATT;
    int tid  = threadIdx.x;
    int wid  = tid >> 5, lane = tid & 31;

    if (tid < AHALO) {
        int tc = t0 - WINc + tid;
        sM[tid] = (tc >= 0 && tc < Tc) ? mask[b * Tc + tc] : 0;
    }
    // stage Q (64 x 128B SW128)
    for (int i = tid; i < 64 * 32; i += 256) {
        int r = i >> 5, j = i & 31;
        uint32_t sw = SW128((uint32_t)((r << 7) + (j << 2)));
        const __half* qr = qkv + (size_t)(b * Tc + t0 + r) * QKVN + h * Dc;
        *(uint32_t*)(dyn + SQ_OFF + sw) = *(const uint32_t*)(qr + j * 2);
    }
    // stage K and V halos (both 112 x 128B SW128, zero pad)
    for (int i = tid; i < AHALO * 32; i += 256) {
        int r = i >> 5, j = i & 31;
        int tc = t0 - WINc + r;
        uint32_t kv = 0, vv = 0;
        if (tc >= 0 && tc < Tc) {
            const __half* kr = qkv + (size_t)(b * Tc + tc) * QKVN + Ec + h * Dc;
            const __half* vr = qkv + (size_t)(b * Tc + tc) * QKVN + 2 * Ec + h * Dc;
            kv = *(const uint32_t*)(kr + j * 2);
            vv = *(const uint32_t*)(vr + j * 2);
        }
        uint32_t sw = SW128((uint32_t)((r << 7) + (j << 2)));
        *(uint32_t*)(dyn + SKH_OFF + sw) = kv;
        *(uint32_t*)(dyn + SVH_OFF + sw) = vv;
    }
    // zero windowed P (64 x 144B)
    for (int i = tid; i < 64 * PPITCH / 4; i += 256)
        ((uint32_t*)(dyn + SP_OFF))[i] = 0u;
    __syncthreads();

    int mat  = lane >> 3;
    int mrow = lane & 7;
    int rsel = (mat & 1) * 8 + mrow;
    int csel = mat >> 1;
    int grp  = lane >> 2;
    int qd   = lane & 3;

    int m0  = (wid >> 1) * 16;                  // token group
    int nw0 = (wid & 1) * 32;                   // window-col sub-split

    // ---- MMA1: S[m0..m0+16) x window [m0, m0+64) (this warp: 32 cols) ----
    float acc1[4][4];
#pragma unroll
    for (int j = 0; j < 4; j++)
#pragma unroll
        for (int r = 0; r < 4; r++) acc1[j][r] = 0.f;
#pragma unroll
    for (int kk = 0; kk < 4; kk++) {
        int chunk = 2 * kk + csel;
        uint32_t aq[4];
        {
            uint32_t sw = SW128((uint32_t)((m0 + rsel) << 7) + (chunk << 4));
            ldmx4(aq[0], aq[1], aq[2], aq[3], sb + SQ_OFF + sw);
        }
        uint32_t bk[4][2];
#pragma unroll
        for (int bj = 0; bj < 2; bj++) {
            int krow = m0 + nw0 + bj * 16 + rsel;
            uint32_t sw = SW128((uint32_t)(krow << 7) + (chunk << 4));
            uint32_t r0, r1, r2, r3;
            ldmx4(r0, r1, r2, r3, sb + SKH_OFF + sw);
            bk[2*bj][0] = r0; bk[2*bj][1] = r2; bk[2*bj+1][0] = r1; bk[2*bj+1][1] = r3;
        }
#pragma unroll
        for (int nf = 0; nf < 4; nf++)
            mma16816(acc1[nf], aq, bk[nf]);
    }
    __syncthreads();   // Q/Kh ldmatrix complete -> safe to alias with S

    // write windowed S (scaled), pitch 68 floats
    float* sS = (float*)(dyn + SS_OFF);
#pragma unroll
    for (int nf = 0; nf < 4; nf++) {
        int n = nw0 + nf * 8 + qd * 2;
#pragma unroll
        for (int hf = 0; hf < 2; hf++) {
            int m = m0 + hf * 8 + grp;
            float2 v;
            v.x = acc1[nf][hf * 2 + 0] * 0.125f;
            v.y = acc1[nf][hf * 2 + 1] * 0.125f;
            *(float2*)(sS + m * 68 + n) = v;
        }
    }
    __syncthreads();

    // ---- band softmax: warp per token; window-local band at tt&15 ----
    for (int tt = wid; tt < ATT; tt += 8) {
        int wl = tt & 15;
        const float* srow = sS + tt * 68 + wl;
        float s   = (sM[tt + lane] > 0) ? srow[lane] : -1e9f;
        float s32 = (sM[tt + 32]   > 0) ? srow[32]   : -1e9f;
        float m = s;
#pragma unroll
        for (int o = 16; o > 0; o >>= 1) m = fmaxf(m, __shfl_xor_sync(0xffffffffu, m, o));
        m = fmaxf(m, s32);
        float e  = __expf(s - m);
        float es = e;
#pragma unroll
        for (int o = 16; o > 0; o >>= 1) es += __shfl_xor_sync(0xffffffffu, es, o);
        float e32 = __expf(s32 - m);
        float inv = 1.f / (es + e32);
        __half* prow = (__half*)(dyn + SP_OFF + tt * PPITCH);
        prow[wl + lane] = __float2half_rn(e * inv);
        if (lane == 0) prow[wl + 32] = __float2half_rn(e32 * inv);
    }
    __syncthreads();

    // ---- MMA2: O = P_window @ V_window (B via ldmatrix.trans on V rows) ----
    int n0d = (wid & 1) * 32;
    int g   = lane >> 3, lr = lane & 7;
    float acc2[4][4];
#pragma unroll
    for (int j = 0; j < 4; j++)
#pragma unroll
        for (int r = 0; r < 4; r++) acc2[j][r] = 0.f;
#pragma unroll
    for (int kk = 0; kk < 4; kk++) {
        uint32_t ap[4];
        {
            uint32_t ad = sb + SP_OFF + (uint32_t)((m0 + rsel) * PPITCH + kk * 32 + csel * 16);
            ldmx4(ap[0], ap[1], ap[2], ap[3], ad);
        }
        uint32_t bv[4][2];
#pragma unroll
        for (int bj = 0; bj < 2; bj++) {
            int krow = m0 + kk * 16 + (g & 1) * 8 + lr;         // halo key row (<112)
            int ncol = n0d + bj * 16 + (g >> 1) * 8;            // dim
            uint32_t sw = SW128((uint32_t)(krow << 7) + (uint32_t)(ncol << 1));
            uint32_t r0, r1, r2, r3;
            ldmx4t(r0, r1, r2, r3, sb + SVH_OFF + sw);
            bv[2*bj][0] = r0; bv[2*bj][1] = r1; bv[2*bj+1][0] = r2; bv[2*bj+1][1] = r3;
        }
#pragma unroll
        for (int nf = 0; nf < 4; nf++)
            mma16816(acc2[nf], ap, bv[nf]);
    }

#pragma unroll
    for (int nf = 0; nf < 4; nf++) {
        int n = n0d + nf * 8 + qd * 2;
#pragma unroll
        for (int hf = 0; hf < 2; hf++) {
            int m = m0 + hf * 8 + grp;
            __half2 oh;
            oh.x = __float2half_rn(acc2[nf][hf * 2 + 0]);
            oh.y = __float2half_rn(acc2[nf][hf * 2 + 1]);
            *(__half2*)(ao + (size_t)(b * Tc + t0 + m) * Ec + h * Dc + n) = oh;
        }
    }
}

// ---------------- orchestration ----------------
extern "C" void kernel_launch(void* const* d_in, const int* in_sizes, int n_in,
                              void* d_out, int out_size) {
    const int*   tokens  = (const int*)  d_in[0];
    const int*   attmask = (const int*)  d_in[1];
    const float* tok_emb = (const float*)d_in[2];
    const float* pos_emb = (const float*)d_in[3];
    const float* Wq      = (const float*)d_in[4];
    const float* Wk      = (const float*)d_in[5];
    const float* Wv      = (const float*)d_in[6];
    const float* Wo      = (const float*)d_in[7];
    const float* bo      = (const float*)d_in[8];
    const float* ln1_g   = (const float*)d_in[9];
    const float* ln1_b   = (const float*)d_in[10];
    const float* ln2_g   = (const float*)d_in[11];
    const float* ln2_b   = (const float*)d_in[12];
    const float* W1      = (const float*)d_in[13];
    const float* b1      = (const float*)d_in[14];
    const float* W2      = (const float*)d_in[15];
    const float* b2      = (const float*)d_in[16];

    float* x = (float*)d_out;

    __half *h, *qkv, *ao, *ff, *wt;
    cudaGetSymbolAddress((void**)&h,   g_h);
    cudaGetSymbolAddress((void**)&qkv, g_qkv);
    cudaGetSymbolAddress((void**)&ao,  g_ao);
    cudaGetSymbolAddress((void**)&ff,  g_ff);
    cudaGetSymbolAddress((void**)&wt,  g_wt);

    cudaFuncSetAttribute(mma_gemm<0>, cudaFuncAttributeMaxDynamicSharedMemorySize, GEMM_SMEM);
    cudaFuncSetAttribute(mma_gemm<1>, cudaFuncAttributeMaxDynamicSharedMemorySize, GEMM_SMEM);
    cudaFuncSetAttribute(mma_gemm<2>, cudaFuncAttributeMaxDynamicSharedMemorySize, GEMM_SMEM);
    cudaFuncSetAttribute(attn_kernel, cudaFuncAttributeMaxDynamicSharedMemorySize, ATT_SMEM);

    prep_kernel<<<dim3(1024, 6, Lc), dim3(32, 8)>>>(Wq, Wk, Wv, Wo, W1, W2, wt);
    embed_ln_kernel<<<1024, 256>>>(tokens, tok_emb, pos_emb, ln1_g, ln1_b, x, h);

    for (int l = 0; l < Lc; l++) {
        const __half* w = wt + (size_t)l * WT_LAYER;

        if (l > 0)
            ln_kernel<<<1024, 256>>>(x, ln1_g + l * Ec, ln1_b + l * Ec, h);

        mma_gemm<0><<<dim3(QKVN / GBN, ROWS / GBM), 256, GEMM_SMEM>>>(
            h, w + WT_QKV_OFF, nullptr, nullptr, nullptr, qkv, QKVN, Ec);

        attn_kernel<<<Bc * Hc * (Tc / ATT), 256, ATT_SMEM>>>(qkv, attmask, ao);

        mma_gemm<2><<<dim3(Ec / GBN, ROWS / GBM), 256, GEMM_SMEM>>>(
            ao, w + WT_WO_OFF, bo + l * Ec, x, x, nullptr, Ec, Ec);

        ln_kernel<<<1024, 256>>>(x, ln2_g + l * Ec, ln2_b + l * Ec, h);

        mma_gemm<1><<<dim3(FFc / GBN, ROWS / GBM), 256, GEMM_SMEM>>>(
            h, w + WT_W1_OFF, b1 + l * FFc, nullptr, nullptr, ff, FFc, Ec);

        mma_gemm<2><<<dim3(Ec / GBN, ROWS / GBM), 256, GEMM_SMEM>>>(
            ff, w + WT_W2_OFF, b2 + l * Ec, x, x, nullptr, Ec, FFc);
    }
    (void)in_sizes; (void)n_in; (void)out_size;
}